// round 3
// baseline (speedup 1.0000x reference)
#include <cuda_runtime.h>
#include <cuda_bf16.h>
#include <math.h>

// Problem constants (capacities; runtime sizes derived from in_sizes)
#define MAXN 50000
#define MAXE 800000
#define MAXG 64

// ---------------- scratch (static device allocations are the sanctioned path) ----
__device__ float g_h[(size_t)MAXN * 256];    // GEMM output (pre-aggregation)
__device__ float g_agg[(size_t)MAXN * 256];  // aggregation output (layer input)
__device__ float g_dinv[MAXN];
__device__ int   g_deg[MAXN];
__device__ int   g_rowptr[MAXN + 1];
__device__ int   g_fill[MAXN];
__device__ int   g_col[MAXE];
__device__ float g_pool[MAXG * 64];
__device__ int   g_cnt[MAXG];
__device__ int   g_is64;

// ---------------- index dtype detection (int64 vs int32) -------------------------
__global__ void detect_k(const void* ei) {
    __shared__ int nz;
    if (threadIdx.x == 0) nz = 0;
    __syncthreads();
    const int* p = (const int*)ei;
    // If data is int64 (values < 2^31), every odd 32-bit word is 0.
    // If data is int32, odd words are random node ids in [0, 50000) -> ~never all zero.
    if (p[2 * threadIdx.x + 1] != 0) atomicAdd(&nz, 1);
    __syncthreads();
    if (threadIdx.x == 0) g_is64 = (nz == 0) ? 1 : 0;
}

__device__ __forceinline__ int load_idx(const void* p, long long i, int is64) {
    if (is64) return (int)((const long long*)p)[i];
    return ((const int*)p)[i];
}

// ---------------- init ------------------------------------------------------------
__global__ void init_k(int n) {
    int i = blockIdx.x * blockDim.x + threadIdx.x;
    int stride = gridDim.x * blockDim.x;
    for (; i < n; i += stride) {
        g_deg[i]  = 1;   // self-loop
        g_fill[i] = 0;
        if (i < MAXG * 64) g_pool[i] = 0.0f;
        if (i < MAXG) g_cnt[i] = 0;
    }
}

// ---------------- degree histogram ------------------------------------------------
__global__ void deg_k(const void* ei, int E) {
    int e = blockIdx.x * blockDim.x + threadIdx.x;
    if (e >= E) return;
    int is64 = g_is64;
    int d = load_idx(ei, (long long)E + e, is64);  // dst row of edge_index
    atomicAdd(&g_deg[d], 1);
}

__global__ void dinv_k(int n) {
    int i = blockIdx.x * blockDim.x + threadIdx.x;
    if (i < n) g_dinv[i] = rsqrtf((float)g_deg[i]);
}

// ---------------- single-block exclusive scan of (deg-1) -> rowptr ----------------
__global__ void scan_k(int n) {
    __shared__ int part[1024];
    int t = threadIdx.x;
    int C = (n + 1023) / 1024;
    int lo = t * C;
    int hi = min(lo + C, n);
    int s = 0;
    for (int i = lo; i < hi; i++) s += g_deg[i] - 1;
    part[t] = s;
    __syncthreads();
    for (int off = 1; off < 1024; off <<= 1) {
        int v = (t >= off) ? part[t - off] : 0;
        __syncthreads();
        part[t] += v;
        __syncthreads();
    }
    int run = (t == 0) ? 0 : part[t - 1];
    for (int i = lo; i < hi; i++) {
        g_rowptr[i] = run;
        run += g_deg[i] - 1;
    }
    if (t == 1023) g_rowptr[n] = part[1023];
}

// ---------------- scatter edges into CSR-by-dst -----------------------------------
__global__ void scat_k(const void* ei, int E) {
    int e = blockIdx.x * blockDim.x + threadIdx.x;
    if (e >= E) return;
    int is64 = g_is64;
    int s = load_idx(ei, e, is64);
    int d = load_idx(ei, (long long)E + e, is64);
    int pos = atomicAdd(&g_fill[d], 1);
    g_col[g_rowptr[d] + pos] = s;
}

// ---------------- SGEMM: C[MxNc] = A[MxK] @ B[KxNc], row-major --------------------
#define BM 64
#define BN 64
#define BK 16
__global__ __launch_bounds__(256) void sgemm_k(const float* __restrict__ A,
                                               const float* __restrict__ B,
                                               float* __restrict__ C,
                                               int M, int K, int Nc) {
    __shared__ float As[BK][BM];
    __shared__ float Bs[BK][BN];
    int t  = threadIdx.x;
    int bx = blockIdx.x;  // tile along Nc
    int by = blockIdx.y;  // tile along M
    int ty = t >> 4, tx = t & 15;
    int rowBase = by * BM;
    int colBase = bx * BN;
    float acc[4][4] = {};

    for (int k0 = 0; k0 < K; k0 += BK) {
#pragma unroll
        for (int i = 0; i < 4; i++) {
            int e  = t + i * 256;         // 0..1023 over 64x16 A tile
            int rr = e >> 4, kk = e & 15;
            int row = rowBase + rr;
            As[kk][rr] = (row < M) ? A[(size_t)row * K + k0 + kk] : 0.0f;
        }
#pragma unroll
        for (int i = 0; i < 4; i++) {
            int e  = t + i * 256;         // 0..1023 over 16x64 B tile
            int kk = e >> 6, cc = e & 63;
            Bs[kk][cc] = B[(size_t)(k0 + kk) * Nc + colBase + cc];
        }
        __syncthreads();
#pragma unroll
        for (int kk = 0; kk < BK; kk++) {
            float a[4], b[4];
#pragma unroll
            for (int i = 0; i < 4; i++) a[i] = As[kk][ty * 4 + i];
#pragma unroll
            for (int j = 0; j < 4; j++) b[j] = Bs[kk][tx * 4 + j];
#pragma unroll
            for (int i = 0; i < 4; i++)
#pragma unroll
                for (int j = 0; j < 4; j++) acc[i][j] += a[i] * b[j];
        }
        __syncthreads();
    }
#pragma unroll
    for (int i = 0; i < 4; i++) {
        int row = rowBase + ty * 4 + i;
        if (row < M) {
#pragma unroll
            for (int j = 0; j < 4; j++)
                C[(size_t)row * Nc + colBase + tx * 4 + j] = acc[i][j];
        }
    }
}

// ---------------- normalized aggregation + bias + optional relu -------------------
// out[d,f] = act( dinv[d] * ( sum_{s in nbrs(d)} dinv[s]*h[s,f] + dinv[d]*h[d,f] ) + b[f] )
__global__ void agg_k(const float* __restrict__ h, float* __restrict__ out,
                      const float* __restrict__ bias, int F, int relu) {
    int d = blockIdx.x;
    int f = threadIdx.x;  // blockDim.x == F
    __shared__ int   sc[64];
    __shared__ float sw[64];
    float dv  = g_dinv[d];
    float acc = dv * h[(size_t)d * F + f];
    int beg = g_rowptr[d], end = g_rowptr[d + 1];
    for (int j0 = beg; j0 < end; j0 += 64) {
        int m = min(64, end - j0);
        if (f < m) {
            int s = g_col[j0 + f];
            sc[f] = s;
            sw[f] = g_dinv[s];
        }
        __syncthreads();
        for (int j = 0; j < m; j++)
            acc += sw[j] * h[(size_t)sc[j] * F + f];
        __syncthreads();
    }
    float v = dv * acc + bias[f];
    out[(size_t)d * F + f] = relu ? fmaxf(v, 0.0f) : v;
}

// ---------------- global mean pool (accumulate) -----------------------------------
__global__ void pool_k(const float* __restrict__ h, const void* batch, int n) {
    int d = blockIdx.x;
    if (d >= n) return;
    int f = threadIdx.x;  // 64 threads
    int is64 = g_is64;
    int b = load_idx(batch, d, is64);
    atomicAdd(&g_pool[b * 64 + f], h[(size_t)d * 64 + f]);
    if (f == 0) atomicAdd(&g_cnt[b], 1);
}

// ---------------- final head: out[g,c] = (pool[g]/cnt[g]) @ Wl + bl ---------------
__global__ void final_k(const float* __restrict__ Wl, const float* __restrict__ bl,
                        float* __restrict__ out, int G) {
    int t = threadIdx.x;
    if (t >= G * 2) return;
    int g = t >> 1, c = t & 1;
    float cn = fmaxf((float)g_cnt[g], 1.0f);
    float s = 0.0f;
#pragma unroll
    for (int k = 0; k < 64; k++)
        s += (g_pool[g * 64 + k] / cn) * Wl[k * 2 + c];
    out[t] = s + bl[c];
}

// ---------------- launch ----------------------------------------------------------
extern "C" void kernel_launch(void* const* d_in, const int* in_sizes, int n_in,
                              void* d_out, int out_size) {
    const float* x   = (const float*)d_in[0];
    const void*  ei  = d_in[1];  // edge_index [2,E], int64 or int32 (detected)
    const void*  bat = d_in[2];  // batch [N]
    const float* W1  = (const float*)d_in[3];
    const float* b1  = (const float*)d_in[4];
    const float* W2  = (const float*)d_in[5];
    const float* b2  = (const float*)d_in[6];
    const float* W3  = (const float*)d_in[7];
    const float* b3  = (const float*)d_in[8];
    const float* Wl  = (const float*)d_in[9];
    const float* bl  = (const float*)d_in[10];
    float* out = (float*)d_out;

    int n = in_sizes[0] / 512;   // 50000
    int E = in_sizes[1] / 2;     // 800000
    int G = out_size / 2;        // 64

    float *h, *agg, *dinv;
    cudaGetSymbolAddress((void**)&h, g_h);
    cudaGetSymbolAddress((void**)&agg, g_agg);
    cudaGetSymbolAddress((void**)&dinv, g_dinv);
    (void)dinv;

    // --- graph structure (recomputed every call; cheap) ---
    detect_k<<<1, 128>>>(ei);
    init_k<<<256, 256>>>(n);
    deg_k<<<(E + 255) / 256, 256>>>(ei, E);
    dinv_k<<<(n + 255) / 256, 256>>>(n);
    scan_k<<<1, 1024>>>(n);
    scat_k<<<(E + 255) / 256, 256>>>(ei, E);

    // --- layer 1: 512 -> 256 ---
    {
        dim3 grid(256 / BN, (n + BM - 1) / BM);
        sgemm_k<<<grid, 256>>>(x, W1, h, n, 512, 256);
        agg_k<<<n, 256>>>(h, agg, b1, 256, 1);
    }
    // --- layer 2: 256 -> 128 ---
    {
        dim3 grid(128 / BN, (n + BM - 1) / BM);
        sgemm_k<<<grid, 256>>>(agg, W2, h, n, 256, 128);
        agg_k<<<n, 128>>>(h, agg, b2, 128, 1);
    }
    // --- layer 3: 128 -> 64 ---
    {
        dim3 grid(64 / BN, (n + BM - 1) / BM);
        sgemm_k<<<grid, 256>>>(agg, W3, h, n, 128, 64);
        agg_k<<<n, 64>>>(h, agg, b3, 64, 0);
    }
    // --- pool + head ---
    pool_k<<<n, 64>>>(agg, bat, n);
    final_k<<<1, 128>>>(Wl, bl, out, G);
}

// round 4
// speedup vs baseline: 1.2126x; 1.2126x over previous
#include <cuda_runtime.h>
#include <cuda_bf16.h>
#include <math.h>
#include <stdint.h>

#define MAXN 50000
#define MAXE 800000
#define MAXG 64

// ---------------- scratch ---------------------------------------------------------
__device__ float g_h[(size_t)MAXN * 256];    // GEMM output (pre-aggregation)
__device__ float g_agg[(size_t)MAXN * 256];  // aggregation output (layer input)
__device__ float g_dinv[MAXN];
__device__ int   g_deg[MAXN];
__device__ int   g_rowptr[MAXN + 1];
__device__ int   g_fill[MAXN];
__device__ int   g_col[MAXE];
__device__ float g_pool[MAXG * 64];
__device__ int   g_cnt[MAXG];
__device__ int   g_is64;

// ---------------- index dtype detection (int64 vs int32) -------------------------
__global__ void detect_k(const void* ei) {
    __shared__ int nz;
    if (threadIdx.x == 0) nz = 0;
    __syncthreads();
    const int* p = (const int*)ei;
    if (p[2 * threadIdx.x + 1] != 0) atomicAdd(&nz, 1);
    __syncthreads();
    if (threadIdx.x == 0) g_is64 = (nz == 0) ? 1 : 0;
}

__device__ __forceinline__ int load_idx(const void* p, long long i, int is64) {
    if (is64) return (int)((const long long*)p)[i];
    return ((const int*)p)[i];
}

// ---------------- init ------------------------------------------------------------
__global__ void init_k(int n) {
    int i = blockIdx.x * blockDim.x + threadIdx.x;
    int stride = gridDim.x * blockDim.x;
    for (; i < n; i += stride) {
        g_deg[i]  = 1;
        g_fill[i] = 0;
        if (i < MAXG * 64) g_pool[i] = 0.0f;
        if (i < MAXG) g_cnt[i] = 0;
    }
}

__global__ void deg_k(const void* ei, int E) {
    int e = blockIdx.x * blockDim.x + threadIdx.x;
    if (e >= E) return;
    int is64 = g_is64;
    int d = load_idx(ei, (long long)E + e, is64);
    atomicAdd(&g_deg[d], 1);
}

__global__ void dinv_k(int n) {
    int i = blockIdx.x * blockDim.x + threadIdx.x;
    if (i < n) g_dinv[i] = rsqrtf((float)g_deg[i]);
}

// ---------------- single-block exclusive scan of (deg-1) -> rowptr ----------------
__global__ void scan_k(int n) {
    __shared__ int part[1024];
    int t = threadIdx.x;
    int C = (n + 1023) / 1024;
    int lo = t * C;
    int hi = min(lo + C, n);
    int s = 0;
    for (int i = lo; i < hi; i++) s += g_deg[i] - 1;
    part[t] = s;
    __syncthreads();
    for (int off = 1; off < 1024; off <<= 1) {
        int v = (t >= off) ? part[t - off] : 0;
        __syncthreads();
        part[t] += v;
        __syncthreads();
    }
    int run = (t == 0) ? 0 : part[t - 1];
    for (int i = lo; i < hi; i++) {
        g_rowptr[i] = run;
        run += g_deg[i] - 1;
    }
    if (t == 1023) g_rowptr[n] = part[1023];
}

__global__ void scat_k(const void* ei, int E) {
    int e = blockIdx.x * blockDim.x + threadIdx.x;
    if (e >= E) return;
    int is64 = g_is64;
    int s = load_idx(ei, e, is64);
    int d = load_idx(ei, (long long)E + e, is64);
    int pos = atomicAdd(&g_fill[d], 1);
    g_col[g_rowptr[d] + pos] = s;
}

// ---------------- 3xTF32 tensor-core GEMM ----------------------------------------
// C[MxNc] = A[MxK] @ B[KxNc], row-major. Tile 128x64, BK=16, 8 warps (256 thr).
// Each warp: 32x32 = 2 (m16) x 4 (n8) m16n8k8 frags. 3xTF32 split for fp32 accuracy.
#define TBM 128
#define TBN 64
#define TBK 16
#define SA  20   // As row stride (floats): (20*m + k) % 32 conflict-free frag loads
#define SB  68   // Bs row stride (floats): (68*k + n) % 32 conflict-free frag loads

__device__ __forceinline__ float ftf32(float x) {
    uint32_t u;
    asm("cvt.rna.tf32.f32 %0, %1;" : "=r"(u) : "f"(x));
    return __uint_as_float(u);
}

__device__ __forceinline__ void mma_tf32(float* d, const uint32_t* a, const uint32_t* b) {
    asm volatile(
        "mma.sync.aligned.m16n8k8.row.col.f32.tf32.tf32.f32 "
        "{%0,%1,%2,%3}, {%4,%5,%6,%7}, {%8,%9}, {%0,%1,%2,%3};"
        : "+f"(d[0]), "+f"(d[1]), "+f"(d[2]), "+f"(d[3])
        : "r"(a[0]), "r"(a[1]), "r"(a[2]), "r"(a[3]), "r"(b[0]), "r"(b[1]));
}

__global__ __launch_bounds__(256) void tgemm_k(const float* __restrict__ A,
                                               const float* __restrict__ B,
                                               float* __restrict__ C,
                                               int M, int K, int Nc) {
    __shared__ float AsH[TBM * SA];
    __shared__ float AsL[TBM * SA];
    __shared__ float BsH[TBK * SB];
    __shared__ float BsL[TBK * SB];

    int t    = threadIdx.x;
    int wid  = t >> 5, lane = t & 31;
    int wm   = (wid >> 1) * 32;          // warp m offset within tile (0,32,64,96)
    int wn   = (wid & 1) * 32;           // warp n offset within tile (0,32)
    int r    = lane >> 2, c = lane & 3;
    int rowBase = blockIdx.y * TBM;
    int colBase = blockIdx.x * TBN;

    float acc[2][4][4] = {};

    for (int k0 = 0; k0 < K; k0 += TBK) {
        // --- load A tile (128x16) : 2 float4 per thread ---
#pragma unroll
        for (int i = 0; i < 2; i++) {
            int row = (t >> 2) + i * 64;
            int kc  = (t & 3) * 4;
            float4 v = make_float4(0.f, 0.f, 0.f, 0.f);
            int gr = rowBase + row;
            if (gr < M) v = *(const float4*)(A + (size_t)gr * K + k0 + kc);
            float hx = ftf32(v.x), hy = ftf32(v.y), hz = ftf32(v.z), hw = ftf32(v.w);
            AsH[row * SA + kc + 0] = hx;  AsL[row * SA + kc + 0] = ftf32(v.x - hx);
            AsH[row * SA + kc + 1] = hy;  AsL[row * SA + kc + 1] = ftf32(v.y - hy);
            AsH[row * SA + kc + 2] = hz;  AsL[row * SA + kc + 2] = ftf32(v.z - hz);
            AsH[row * SA + kc + 3] = hw;  AsL[row * SA + kc + 3] = ftf32(v.w - hw);
        }
        // --- load B tile (16x64) : 1 float4 per thread ---
        {
            int kk = t >> 4;
            int nc = (t & 15) * 4;
            float4 v = *(const float4*)(B + (size_t)(k0 + kk) * Nc + colBase + nc);
            float hx = ftf32(v.x), hy = ftf32(v.y), hz = ftf32(v.z), hw = ftf32(v.w);
            BsH[kk * SB + nc + 0] = hx;  BsL[kk * SB + nc + 0] = ftf32(v.x - hx);
            BsH[kk * SB + nc + 1] = hy;  BsL[kk * SB + nc + 1] = ftf32(v.y - hy);
            BsH[kk * SB + nc + 2] = hz;  BsL[kk * SB + nc + 2] = ftf32(v.z - hz);
            BsH[kk * SB + nc + 3] = hw;  BsL[kk * SB + nc + 3] = ftf32(v.w - hw);
        }
        __syncthreads();

#pragma unroll
        for (int kk = 0; kk < TBK; kk += 8) {
            uint32_t aH[2][4], aL[2][4], bH[4][2], bL[4][2];
#pragma unroll
            for (int mi = 0; mi < 2; mi++) {
                int m0 = wm + mi * 16 + r;
                aH[mi][0] = __float_as_uint(AsH[(m0)     * SA + kk + c]);
                aH[mi][1] = __float_as_uint(AsH[(m0 + 8) * SA + kk + c]);
                aH[mi][2] = __float_as_uint(AsH[(m0)     * SA + kk + c + 4]);
                aH[mi][3] = __float_as_uint(AsH[(m0 + 8) * SA + kk + c + 4]);
                aL[mi][0] = __float_as_uint(AsL[(m0)     * SA + kk + c]);
                aL[mi][1] = __float_as_uint(AsL[(m0 + 8) * SA + kk + c]);
                aL[mi][2] = __float_as_uint(AsL[(m0)     * SA + kk + c + 4]);
                aL[mi][3] = __float_as_uint(AsL[(m0 + 8) * SA + kk + c + 4]);
            }
#pragma unroll
            for (int ni = 0; ni < 4; ni++) {
                int n0 = wn + ni * 8 + r;
                bH[ni][0] = __float_as_uint(BsH[(kk + c)     * SB + n0]);
                bH[ni][1] = __float_as_uint(BsH[(kk + c + 4) * SB + n0]);
                bL[ni][0] = __float_as_uint(BsL[(kk + c)     * SB + n0]);
                bL[ni][1] = __float_as_uint(BsL[(kk + c + 4) * SB + n0]);
            }
#pragma unroll
            for (int mi = 0; mi < 2; mi++)
#pragma unroll
                for (int ni = 0; ni < 4; ni++) {
                    mma_tf32(acc[mi][ni], aL[mi], bH[ni]);  // lo*hi
                    mma_tf32(acc[mi][ni], aH[mi], bL[ni]);  // hi*lo
                    mma_tf32(acc[mi][ni], aH[mi], bH[ni]);  // hi*hi
                }
        }
        __syncthreads();
    }

    // --- store ---
#pragma unroll
    for (int mi = 0; mi < 2; mi++) {
        int gm0 = rowBase + wm + mi * 16 + r;
#pragma unroll
        for (int ni = 0; ni < 4; ni++) {
            int gn = colBase + wn + ni * 8 + 2 * c;
            if (gm0 < M) {
                C[(size_t)gm0 * Nc + gn]     = acc[mi][ni][0];
                C[(size_t)gm0 * Nc + gn + 1] = acc[mi][ni][1];
            }
            if (gm0 + 8 < M) {
                C[(size_t)(gm0 + 8) * Nc + gn]     = acc[mi][ni][2];
                C[(size_t)(gm0 + 8) * Nc + gn + 1] = acc[mi][ni][3];
            }
        }
    }
}

// ---------------- normalized aggregation + bias + optional relu -------------------
__global__ void agg_k(const float* __restrict__ h, float* __restrict__ out,
                      const float* __restrict__ bias, int F, int relu) {
    int d = blockIdx.x;
    int f = threadIdx.x;  // blockDim.x == F
    __shared__ int   sc[64];
    __shared__ float sw[64];
    float dv  = g_dinv[d];
    float acc = dv * h[(size_t)d * F + f];
    int beg = g_rowptr[d], end = g_rowptr[d + 1];
    for (int j0 = beg; j0 < end; j0 += 64) {
        int m = min(64, end - j0);
        if (f < m) {
            int s = g_col[j0 + f];
            sc[f] = s;
            sw[f] = g_dinv[s];
        }
        __syncthreads();
        for (int j = 0; j < m; j++)
            acc += sw[j] * h[(size_t)sc[j] * F + f];
        __syncthreads();
    }
    float v = dv * acc + bias[f];
    out[(size_t)d * F + f] = relu ? fmaxf(v, 0.0f) : v;
}

// ---------------- global mean pool (accumulate) -----------------------------------
__global__ void pool_k(const float* __restrict__ h, const void* batch, int n) {
    int d = blockIdx.x;
    if (d >= n) return;
    int f = threadIdx.x;  // 64 threads
    int is64 = g_is64;
    int b = load_idx(batch, d, is64);
    atomicAdd(&g_pool[b * 64 + f], h[(size_t)d * 64 + f]);
    if (f == 0) atomicAdd(&g_cnt[b], 1);
}

// ---------------- final head ------------------------------------------------------
__global__ void final_k(const float* __restrict__ Wl, const float* __restrict__ bl,
                        float* __restrict__ out, int G) {
    int t = threadIdx.x;
    if (t >= G * 2) return;
    int g = t >> 1, c = t & 1;
    float cn = fmaxf((float)g_cnt[g], 1.0f);
    float s = 0.0f;
#pragma unroll
    for (int k = 0; k < 64; k++)
        s += (g_pool[g * 64 + k] / cn) * Wl[k * 2 + c];
    out[t] = s + bl[c];
}

// ---------------- launch ----------------------------------------------------------
extern "C" void kernel_launch(void* const* d_in, const int* in_sizes, int n_in,
                              void* d_out, int out_size) {
    const float* x   = (const float*)d_in[0];
    const void*  ei  = d_in[1];
    const void*  bat = d_in[2];
    const float* W1  = (const float*)d_in[3];
    const float* b1  = (const float*)d_in[4];
    const float* W2  = (const float*)d_in[5];
    const float* b2  = (const float*)d_in[6];
    const float* W3  = (const float*)d_in[7];
    const float* b3  = (const float*)d_in[8];
    const float* Wl  = (const float*)d_in[9];
    const float* bl  = (const float*)d_in[10];
    float* out = (float*)d_out;

    int n = in_sizes[0] / 512;   // 50000
    int E = in_sizes[1] / 2;     // 800000
    int G = out_size / 2;        // 64

    float *h, *agg;
    cudaGetSymbolAddress((void**)&h, g_h);
    cudaGetSymbolAddress((void**)&agg, g_agg);

    // --- graph structure ---
    detect_k<<<1, 128>>>(ei);
    init_k<<<256, 256>>>(n);
    deg_k<<<(E + 255) / 256, 256>>>(ei, E);
    dinv_k<<<(n + 255) / 256, 256>>>(n);
    scan_k<<<1, 1024>>>(n);
    scat_k<<<(E + 255) / 256, 256>>>(ei, E);

    int gy = (n + TBM - 1) / TBM;

    // --- layer 1: 512 -> 256 ---
    {
        dim3 grid(256 / TBN, gy);
        tgemm_k<<<grid, 256>>>(x, W1, h, n, 512, 256);
        agg_k<<<n, 256>>>(h, agg, b1, 256, 1);
    }
    // --- layer 2: 256 -> 128 ---
    {
        dim3 grid(128 / TBN, gy);
        tgemm_k<<<grid, 256>>>(agg, W2, h, n, 256, 128);
        agg_k<<<n, 128>>>(h, agg, b2, 128, 1);
    }
    // --- layer 3: 128 -> 64 ---
    {
        dim3 grid(64 / TBN, gy);
        tgemm_k<<<grid, 256>>>(agg, W3, h, n, 128, 64);
        agg_k<<<n, 64>>>(h, agg, b3, 64, 0);
    }
    // --- pool + head ---
    pool_k<<<n, 64>>>(agg, bat, n);
    final_k<<<1, 128>>>(Wl, bl, out, G);
}

// round 7
// speedup vs baseline: 1.9396x; 1.5996x over previous
#include <cuda_runtime.h>
#include <cuda_bf16.h>
#include <math.h>
#include <stdint.h>

#define MAXN 50000
#define MAXE 800000
#define MAXG 64

// ---------------- scratch ---------------------------------------------------------
__device__ float g_h[(size_t)MAXN * 256];    // GEMM output (pre-aggregation)
__device__ float g_agg[(size_t)MAXN * 256];  // aggregation output (layer input)
__device__ float g_dinv[MAXN];
__device__ int   g_deg[MAXN];
__device__ int   g_rowptr[MAXN + 1];
__device__ int   g_fill[MAXN];
__device__ int   g_col[MAXE];
__device__ float g_pool[MAXG * 64];
__device__ int   g_cnt[MAXG];
__device__ int   g_is64;

// ---------------- index dtype detection (int64 vs int32) -------------------------
__global__ void detect_k(const void* ei) {
    __shared__ int nz;
    if (threadIdx.x == 0) nz = 0;
    __syncthreads();
    const int* p = (const int*)ei;
    if (p[2 * threadIdx.x + 1] != 0) atomicAdd(&nz, 1);
    __syncthreads();
    if (threadIdx.x == 0) g_is64 = (nz == 0) ? 1 : 0;
}

__device__ __forceinline__ int load_idx(const void* p, long long i, int is64) {
    if (is64) return (int)((const long long*)p)[i];
    return ((const int*)p)[i];
}

// ---------------- init ------------------------------------------------------------
__global__ void init_k(int n) {
    int i = blockIdx.x * blockDim.x + threadIdx.x;
    int stride = gridDim.x * blockDim.x;
    for (; i < n; i += stride) {
        g_deg[i]  = 1;
        g_fill[i] = 0;
        if (i < MAXG * 64) g_pool[i] = 0.0f;
        if (i < MAXG) g_cnt[i] = 0;
    }
}

__global__ void deg_k(const void* ei, int E) {
    int e = blockIdx.x * blockDim.x + threadIdx.x;
    if (e >= E) return;
    int is64 = g_is64;
    int d = load_idx(ei, (long long)E + e, is64);
    atomicAdd(&g_deg[d], 1);
}

__global__ void dinv_k(int n) {
    int i = blockIdx.x * blockDim.x + threadIdx.x;
    if (i < n) g_dinv[i] = rsqrtf((float)g_deg[i]);
}

// ---------------- single-block exclusive scan of (deg-1) -> rowptr ----------------
__global__ void scan_k(int n) {
    __shared__ int part[1024];
    int t = threadIdx.x;
    int C = (n + 1023) / 1024;
    int lo = t * C;
    int hi = min(lo + C, n);
    int s = 0;
    for (int i = lo; i < hi; i++) s += g_deg[i] - 1;
    part[t] = s;
    __syncthreads();
    for (int off = 1; off < 1024; off <<= 1) {
        int v = (t >= off) ? part[t - off] : 0;
        __syncthreads();
        part[t] += v;
        __syncthreads();
    }
    int run = (t == 0) ? 0 : part[t - 1];
    for (int i = lo; i < hi; i++) {
        g_rowptr[i] = run;
        run += g_deg[i] - 1;
    }
    if (t == 1023) g_rowptr[n] = part[1023];
}

__global__ void scat_k(const void* ei, int E) {
    int e = blockIdx.x * blockDim.x + threadIdx.x;
    if (e >= E) return;
    int is64 = g_is64;
    int s = load_idx(ei, e, is64);
    int d = load_idx(ei, (long long)E + e, is64);
    int pos = atomicAdd(&g_fill[d], 1);
    g_col[g_rowptr[d] + pos] = s;
}

// ---------------- 3xBF16 tensor-core GEMM ----------------------------------------
// C[MxNc] = A[MxK] @ B[KxNc], row-major. Tile 128x64, BK=32, 8 warps.
// bf16 split: a = aH + aL; C += aH*bH + aH*bL + aL*bH  (fp16-grade accuracy).
// Smem layout packs k-pairs as bfloat162: As2[k2][m] (stride 136), Bs2[k2][n] (68).
// All fragment LDS.32 and tile STS.32 are bank-conflict-free by construction.
#define BM 128
#define BN 64
#define BK 32
#define NK2 16      // BK/2 k2-slots
#define SMA 136     // As2 row stride (bfloat162 elems)
#define SNB 68      // Bs2 row stride

__device__ __forceinline__ void mma_bf16(float* d, const uint32_t* a, const uint32_t* b) {
    asm volatile(
        "mma.sync.aligned.m16n8k16.row.col.f32.bf16.bf16.f32 "
        "{%0,%1,%2,%3}, {%4,%5,%6,%7}, {%8,%9}, {%0,%1,%2,%3};"
        : "+f"(d[0]), "+f"(d[1]), "+f"(d[2]), "+f"(d[3])
        : "r"(a[0]), "r"(a[1]), "r"(a[2]), "r"(a[3]), "r"(b[0]), "r"(b[1]));
}

__device__ __forceinline__ uint32_t pack_hi(float x, float y) {
    __nv_bfloat162 v;
    v.x = __float2bfloat16(x);
    v.y = __float2bfloat16(y);
    return *(uint32_t*)&v;
}
__device__ __forceinline__ uint32_t pack_lo(float x, float y) {
    __nv_bfloat162 v;
    float hx = __bfloat162float(__float2bfloat16(x));
    float hy = __bfloat162float(__float2bfloat16(y));
    v.x = __float2bfloat16(x - hx);
    v.y = __float2bfloat16(y - hy);
    return *(uint32_t*)&v;
}

__global__ __launch_bounds__(256) void tgemm_k(const float* __restrict__ A,
                                               const float* __restrict__ B,
                                               float* __restrict__ C,
                                               int M, int K, int Nc) {
    __shared__ uint32_t AsH[NK2 * SMA];
    __shared__ uint32_t AsL[NK2 * SMA];
    __shared__ uint32_t BsH[NK2 * SNB];
    __shared__ uint32_t BsL[NK2 * SNB];

    int t = threadIdx.x, wid = t >> 5, lane = t & 31;
    int wm = (wid >> 1) * 32;       // warp m offset (0,32,64,96)
    int wn = (wid & 1) * 32;        // warp n offset (0,32)
    int r = lane >> 2, c = lane & 3;
    int rowBase = blockIdx.y * BM;
    int colBase = blockIdx.x * BN;

    float acc[2][4][4] = {};

    float2 aReg[8];                 // A: e = t + i*256 ; k2 = e&15, m = e>>4
    float  bReg[8];                 // B: e = t + i*256 ; k2 = e>>6, n = e&63 (2 floats each)

    // ---- prefetch first tile ----
    {
#pragma unroll
        for (int i = 0; i < 8; i++) {
            int e = t + i * 256;
            int k2 = e & 15, m = e >> 4;
            int gr = rowBase + m;
            aReg[i] = (gr < M) ? *(const float2*)(A + (size_t)gr * K + 2 * k2)
                               : make_float2(0.f, 0.f);
        }
#pragma unroll
        for (int i = 0; i < 4; i++) {
            int e = t + i * 256;
            int k2 = e >> 6, nn = e & 63;
            bReg[2 * i]     = B[(size_t)(2 * k2)     * Nc + colBase + nn];
            bReg[2 * i + 1] = B[(size_t)(2 * k2 + 1) * Nc + colBase + nn];
        }
    }

    for (int k0 = 0; k0 < K; k0 += BK) {
        // ---- store staged tile (convert to bf16 hi/lo) ----
#pragma unroll
        for (int i = 0; i < 8; i++) {
            int e = t + i * 256;
            int k2 = e & 15, m = e >> 4;
            AsH[k2 * SMA + m] = pack_hi(aReg[i].x, aReg[i].y);
            AsL[k2 * SMA + m] = pack_lo(aReg[i].x, aReg[i].y);
        }
#pragma unroll
        for (int i = 0; i < 4; i++) {
            int e = t + i * 256;
            int k2 = e >> 6, nn = e & 63;
            BsH[k2 * SNB + nn] = pack_hi(bReg[2 * i], bReg[2 * i + 1]);
            BsL[k2 * SNB + nn] = pack_lo(bReg[2 * i], bReg[2 * i + 1]);
        }
        __syncthreads();

        // ---- prefetch next tile (global latency hidden behind MMAs) ----
        if (k0 + BK < K) {
            int kn = k0 + BK;
#pragma unroll
            for (int i = 0; i < 8; i++) {
                int e = t + i * 256;
                int k2 = e & 15, m = e >> 4;
                int gr = rowBase + m;
                aReg[i] = (gr < M) ? *(const float2*)(A + (size_t)gr * K + kn + 2 * k2)
                                   : make_float2(0.f, 0.f);
            }
#pragma unroll
            for (int i = 0; i < 4; i++) {
                int e = t + i * 256;
                int k2 = e >> 6, nn = e & 63;
                bReg[2 * i]     = B[(size_t)(kn + 2 * k2)     * Nc + colBase + nn];
                bReg[2 * i + 1] = B[(size_t)(kn + 2 * k2 + 1) * Nc + colBase + nn];
            }
        }

        // ---- MMA: 2 ksteps of k16 ----
#pragma unroll
        for (int ks = 0; ks < 2; ks++) {
            int kb = ks * 8;  // k2 base
            uint32_t aH[2][4], aL[2][4], bH[4][2], bL[4][2];
#pragma unroll
            for (int mi = 0; mi < 2; mi++) {
                int m0 = wm + mi * 16 + r;
                aH[mi][0] = AsH[(kb + c)     * SMA + m0];
                aH[mi][1] = AsH[(kb + c)     * SMA + m0 + 8];
                aH[mi][2] = AsH[(kb + c + 4) * SMA + m0];
                aH[mi][3] = AsH[(kb + c + 4) * SMA + m0 + 8];
                aL[mi][0] = AsL[(kb + c)     * SMA + m0];
                aL[mi][1] = AsL[(kb + c)     * SMA + m0 + 8];
                aL[mi][2] = AsL[(kb + c + 4) * SMA + m0];
                aL[mi][3] = AsL[(kb + c + 4) * SMA + m0 + 8];
            }
#pragma unroll
            for (int ni = 0; ni < 4; ni++) {
                int n0 = wn + ni * 8 + r;
                bH[ni][0] = BsH[(kb + c)     * SNB + n0];
                bH[ni][1] = BsH[(kb + c + 4) * SNB + n0];
                bL[ni][0] = BsL[(kb + c)     * SNB + n0];
                bL[ni][1] = BsL[(kb + c + 4) * SNB + n0];
            }
#pragma unroll
            for (int mi = 0; mi < 2; mi++)
#pragma unroll
                for (int ni = 0; ni < 4; ni++) {
                    mma_bf16(acc[mi][ni], aL[mi], bH[ni]);
                    mma_bf16(acc[mi][ni], aH[mi], bL[ni]);
                    mma_bf16(acc[mi][ni], aH[mi], bH[ni]);
                }
        }
        __syncthreads();
    }

    // ---- store C ----
#pragma unroll
    for (int mi = 0; mi < 2; mi++) {
        int gm0 = rowBase + wm + mi * 16 + r;
#pragma unroll
        for (int ni = 0; ni < 4; ni++) {
            int gn = colBase + wn + ni * 8 + 2 * c;
            if (gm0 < M) {
                C[(size_t)gm0 * Nc + gn]     = acc[mi][ni][0];
                C[(size_t)gm0 * Nc + gn + 1] = acc[mi][ni][1];
            }
            if (gm0 + 8 < M) {
                C[(size_t)(gm0 + 8) * Nc + gn]     = acc[mi][ni][2];
                C[(size_t)(gm0 + 8) * Nc + gn + 1] = acc[mi][ni][3];
            }
        }
    }
}

// ---------------- normalized aggregation (float4-vectorized) ----------------------
// out[d,:] = act( dinv[d]*( sum_s dinv[s]*h[s,:] + dinv[d]*h[d,:] ) + b )
__global__ __launch_bounds__(256) void agg_k(const float* __restrict__ h,
                                             float* __restrict__ out,
                                             const float* __restrict__ bias,
                                             int F, int relu, int n) {
    int tpn   = F >> 2;                    // threads per node (64/32/16)
    int npb   = 256 / tpn;                 // nodes per block
    int local = threadIdx.x / tpn;
    int fl    = threadIdx.x - local * tpn;
    int d     = blockIdx.x * npb + local;
    if (d >= n) return;

    const float4* hp = (const float4*)h;
    float dv = g_dinv[d];
    float4 acc = hp[(size_t)d * tpn + fl];
    acc.x *= dv; acc.y *= dv; acc.z *= dv; acc.w *= dv;

    int beg = g_rowptr[d], end = g_rowptr[d + 1];
    int j = beg;
    for (; j + 1 < end; j += 2) {
        int s0 = g_col[j], s1 = g_col[j + 1];
        float w0 = g_dinv[s0], w1 = g_dinv[s1];
        float4 v0 = hp[(size_t)s0 * tpn + fl];
        float4 v1 = hp[(size_t)s1 * tpn + fl];
        acc.x += w0 * v0.x + w1 * v1.x;
        acc.y += w0 * v0.y + w1 * v1.y;
        acc.z += w0 * v0.z + w1 * v1.z;
        acc.w += w0 * v0.w + w1 * v1.w;
    }
    if (j < end) {
        int s = g_col[j];
        float w = g_dinv[s];
        float4 v = hp[(size_t)s * tpn + fl];
        acc.x += w * v.x; acc.y += w * v.y; acc.z += w * v.z; acc.w += w * v.w;
    }

    float4 b4 = ((const float4*)bias)[fl];
    float4 o;
    o.x = dv * acc.x + b4.x;
    o.y = dv * acc.y + b4.y;
    o.z = dv * acc.z + b4.z;
    o.w = dv * acc.w + b4.w;
    if (relu) {
        o.x = fmaxf(o.x, 0.f); o.y = fmaxf(o.y, 0.f);
        o.z = fmaxf(o.z, 0.f); o.w = fmaxf(o.w, 0.f);
    }
    ((float4*)out)[(size_t)d * tpn + fl] = o;
}

// ---------------- global mean pool (float4, accumulate) ---------------------------
__global__ void pool_k(const float* __restrict__ h, const void* batch, int n) {
    int t  = threadIdx.x;
    int d  = blockIdx.x * 16 + (t >> 4);
    int fl = t & 15;
    if (d >= n) return;
    int is64 = g_is64;
    int b = load_idx(batch, d, is64);
    float4 v = ((const float4*)h)[(size_t)d * 16 + fl];
    atomicAdd(&g_pool[b * 64 + fl * 4 + 0], v.x);
    atomicAdd(&g_pool[b * 64 + fl * 4 + 1], v.y);
    atomicAdd(&g_pool[b * 64 + fl * 4 + 2], v.z);
    atomicAdd(&g_pool[b * 64 + fl * 4 + 3], v.w);
    if (fl == 0) atomicAdd(&g_cnt[b], 1);
}

// ---------------- final head ------------------------------------------------------
__global__ void final_k(const float* __restrict__ Wl, const float* __restrict__ bl,
                        float* __restrict__ out, int G) {
    int t = threadIdx.x;
    if (t >= G * 2) return;
    int g = t >> 1, c = t & 1;
    float cn = fmaxf((float)g_cnt[g], 1.0f);
    float s = 0.0f;
#pragma unroll
    for (int k = 0; k < 64; k++)
        s += (g_pool[g * 64 + k] / cn) * Wl[k * 2 + c];
    out[t] = s + bl[c];
}

// ---------------- launch ----------------------------------------------------------
extern "C" void kernel_launch(void* const* d_in, const int* in_sizes, int n_in,
                              void* d_out, int out_size) {
    const float* x   = (const float*)d_in[0];
    const void*  ei  = d_in[1];
    const void*  bat = d_in[2];
    const float* W1  = (const float*)d_in[3];
    const float* b1  = (const float*)d_in[4];
    const float* W2  = (const float*)d_in[5];
    const float* b2  = (const float*)d_in[6];
    const float* W3  = (const float*)d_in[7];
    const float* b3  = (const float*)d_in[8];
    const float* Wl  = (const float*)d_in[9];
    const float* bl  = (const float*)d_in[10];
    float* out = (float*)d_out;

    int n = in_sizes[0] / 512;   // 50000
    int E = in_sizes[1] / 2;     // 800000
    int G = out_size / 2;        // 64

    float *h, *agg;
    cudaGetSymbolAddress((void**)&h, g_h);
    cudaGetSymbolAddress((void**)&agg, g_agg);

    int gy = (n + BM - 1) / BM;

    // graph build interleaved with layer-1 GEMM (GEMM is independent of the graph;
    // placing it 4th also lands it in ncu's captured-launch slot for diagnostics)
    detect_k<<<1, 128>>>(ei);
    init_k<<<256, 256>>>(n);
    deg_k<<<(E + 255) / 256, 256>>>(ei, E);
    {
        dim3 grid(256 / BN, gy);
        tgemm_k<<<grid, 256>>>(x, W1, h, n, 512, 256);
    }
    dinv_k<<<(n + 255) / 256, 256>>>(n);
    scan_k<<<1, 1024>>>(n);
    scat_k<<<(E + 255) / 256, 256>>>(ei, E);

    // --- layer 1 aggregation: F=256, 4 nodes/block ---
    agg_k<<<(n + 3) / 4, 256>>>(h, agg, b1, 256, 1, n);

    // --- layer 2: 256 -> 128 ---
    {
        dim3 grid(128 / BN, gy);
        tgemm_k<<<grid, 256>>>(agg, W2, h, n, 256, 128);
        agg_k<<<(n + 7) / 8, 256>>>(h, agg, b2, 128, 1, n);
    }
    // --- layer 3: 128 -> 64 ---
    {
        dim3 grid(64 / BN, gy);
        tgemm_k<<<grid, 256>>>(agg, W3, h, n, 128, 64);
        agg_k<<<(n + 15) / 16, 256>>>(h, agg, b3, 64, 0, n);
    }
    // --- pool + head ---
    pool_k<<<(n + 15) / 16, 256>>>(agg, bat, n);
    final_k<<<1, 128>>>(Wl, bl, out, G);
}